// round 1
// baseline (speedup 1.0000x reference)
#include <cuda_runtime.h>

// ---------------------------------------------------------------------------
// Problem constants:  B=2, S=2048, D=1024, H=16, HD=64, RANK=8, ALPHA=8
// qkv layout: [B*S, 3*D] rows; Q cols [0,1024), K cols [1024,2048), V [2048,3072)
// ---------------------------------------------------------------------------

__device__ __align__(256) float g_xa [4096 * 8];
__device__ __align__(256) float g_qkv[4096 * 3072];
__device__ __align__(256) float g_ctx[4096 * 1024];

// ---------------------------------------------------------------------------
// xa = x @ A_lora   ([4096,1024] @ [1024,8] -> [4096,8])
// one block per row, 128 threads
// ---------------------------------------------------------------------------
__global__ __launch_bounds__(128) void xa_kernel(const float* __restrict__ x,
                                                 const float* __restrict__ Al,
                                                 float* __restrict__ xa)
{
    const int m   = blockIdx.x;
    const int tid = threadIdx.x;
    float acc[8];
#pragma unroll
    for (int r = 0; r < 8; r++) acc[r] = 0.f;

    const float* xr = x + (size_t)m * 1024;
    for (int k = tid; k < 1024; k += 128) {
        const float xv = xr[k];
        const float4 a0 = *(const float4*)(Al + (size_t)k * 8);
        const float4 a1 = *(const float4*)(Al + (size_t)k * 8 + 4);
        acc[0] = fmaf(xv, a0.x, acc[0]);
        acc[1] = fmaf(xv, a0.y, acc[1]);
        acc[2] = fmaf(xv, a0.z, acc[2]);
        acc[3] = fmaf(xv, a0.w, acc[3]);
        acc[4] = fmaf(xv, a1.x, acc[4]);
        acc[5] = fmaf(xv, a1.y, acc[5]);
        acc[6] = fmaf(xv, a1.z, acc[6]);
        acc[7] = fmaf(xv, a1.w, acc[7]);
    }
#pragma unroll
    for (int off = 16; off > 0; off >>= 1)
#pragma unroll
        for (int r = 0; r < 8; r++)
            acc[r] += __shfl_xor_sync(0xffffffffu, acc[r], off);

    __shared__ float red[4][8];
    if ((tid & 31) == 0)
#pragma unroll
        for (int r = 0; r < 8; r++) red[tid >> 5][r] = acc[r];
    __syncthreads();
    if (tid < 8)
        xa[(size_t)m * 8 + tid] = red[0][tid] + red[1][tid] + red[2][tid] + red[3][tid];
}

// ---------------------------------------------------------------------------
// C[M,N] = A[M,K] @ B[K,N] + bias[N]  (+ ALPHA * xa[M,8] @ Bl[8,N] if LORA)
// 128x128 block tile, BK=8, 256 threads, 8x8 per thread.
// All dims divisible by 128/8 here — no bounds checks.
// ---------------------------------------------------------------------------
template<bool LORA>
__global__ __launch_bounds__(256) void sgemm128(
    const float* __restrict__ A, const float* __restrict__ B,
    const float* __restrict__ bias,
    const float* __restrict__ xa, const float* __restrict__ Bl,
    float* __restrict__ C, int M, int N, int K)
{
    __shared__ float As[8][128];
    __shared__ float Bs[8][132];

    const int tid = threadIdx.x;
    const int tx = tid & 15, ty = tid >> 4;
    const int bm = blockIdx.y, bn = blockIdx.x;

    const int arow = tid >> 1, acol = (tid & 1) << 2;
    const int brow = tid >> 5, bcol = (tid & 31) << 2;

    const float* Ap = A + (size_t)(bm * 128 + arow) * K + acol;
    const float* Bp = B + (size_t)brow * N + bn * 128 + bcol;

    float acc[8][8];
#pragma unroll
    for (int i = 0; i < 8; i++)
#pragma unroll
        for (int j = 0; j < 8; j++) acc[i][j] = 0.f;

    for (int k0 = 0; k0 < K; k0 += 8) {
        const float4 av = *(const float4*)(Ap + k0);
        const float4 bv = *(const float4*)(Bp + (size_t)k0 * N);
        __syncthreads();
        As[acol + 0][arow] = av.x;
        As[acol + 1][arow] = av.y;
        As[acol + 2][arow] = av.z;
        As[acol + 3][arow] = av.w;
        *(float4*)&Bs[brow][bcol] = bv;
        __syncthreads();
#pragma unroll
        for (int kk = 0; kk < 8; kk++) {
            float a[8], b[8];
            *(float4*)&a[0] = *(const float4*)&As[kk][ty * 8];
            *(float4*)&a[4] = *(const float4*)&As[kk][ty * 8 + 4];
            *(float4*)&b[0] = *(const float4*)&Bs[kk][tx * 8];
            *(float4*)&b[4] = *(const float4*)&Bs[kk][tx * 8 + 4];
#pragma unroll
            for (int i = 0; i < 8; i++)
#pragma unroll
                for (int j = 0; j < 8; j++)
                    acc[i][j] = fmaf(a[i], b[j], acc[i][j]);
        }
    }

    const int mbase = bm * 128 + ty * 8;
    const int nbase = bn * 128 + tx * 8;

    float bb[8];
#pragma unroll
    for (int j = 0; j < 8; j++) bb[j] = bias[nbase + j];

    if (LORA) {
#pragma unroll
        for (int i = 0; i < 8; i++) {
            const float* xr = xa + (size_t)(mbase + i) * 8;
#pragma unroll
            for (int r = 0; r < 8; r++) {
                const float xv = xr[r] * 8.0f;   // ALPHA folded in
                const float* blr = Bl + (size_t)r * N + nbase;
#pragma unroll
                for (int j = 0; j < 8; j++)
                    acc[i][j] = fmaf(xv, blr[j], acc[i][j]);
            }
        }
    }

#pragma unroll
    for (int i = 0; i < 8; i++) {
        float4 o0, o1;
        o0.x = acc[i][0] + bb[0];
        o0.y = acc[i][1] + bb[1];
        o0.z = acc[i][2] + bb[2];
        o0.w = acc[i][3] + bb[3];
        o1.x = acc[i][4] + bb[4];
        o1.y = acc[i][5] + bb[5];
        o1.z = acc[i][6] + bb[6];
        o1.w = acc[i][7] + bb[7];
        float* cp = C + (size_t)(mbase + i) * N + nbase;
        *(float4*)cp       = o0;
        *(float4*)(cp + 4) = o1;
    }
}

// ---------------------------------------------------------------------------
// Causal flash attention, fp32. HD=64, S=2048, query tiles of 64 rows.
// grid = (S/64, H, B), 256 threads (16x16). Each thread owns a 4x4 micro-tile:
//   rows  r = ty*4 + i
//   cols  c = tx + 16*j   (strided mapping -> conflict-free LDS.128 on K/V)
// scores = (q.k)/8 for valid, exp->0 for masked (matches (qk-1e9)/8 exactly).
// ---------------------------------------------------------------------------
__global__ __launch_bounds__(256) void flash_kernel(const float* __restrict__ qkv,
                                                    float* __restrict__ ctx)
{
    extern __shared__ float sm[];
    const int PIT = 68;                        // row pitch (floats), mult of 4
    float* Qs = sm;
    float* Ks = sm + 64 * PIT;
    float* Vs = sm + 2 * 64 * PIT;
    float* Ps = sm + 3 * 64 * PIT;

    const int tid = threadIdx.x;
    const int tx = tid & 15, ty = tid >> 4;
    const int qt = blockIdx.x, h = blockIdx.y, b = blockIdx.z;
    const int q0 = qt * 64;

    const float* qb = qkv + (size_t)b * 2048 * 3072 + h * 64;
    const float* kb = qb + 1024;
    const float* vb = qb + 2048;

    // load Q tile [64 x 64]
#pragma unroll
    for (int it = 0; it < 4; it++) {
        const int i  = tid + it * 256;         // float4 index 0..1023
        const int r  = i >> 4;
        const int c4 = (i & 15) << 2;
        *(float4*)&Qs[r * PIT + c4] =
            *(const float4*)(qb + (size_t)(q0 + r) * 3072 + c4);
    }

    float O[4][4];
    float mrow[4], lrow[4];
#pragma unroll
    for (int i = 0; i < 4; i++) {
        mrow[i] = -3.0e38f;
        lrow[i] = 0.f;
#pragma unroll
        for (int j = 0; j < 4; j++) O[i][j] = 0.f;
    }
    __syncthreads();

    for (int kt = 0; kt <= qt; kt++) {
        const int k0 = kt * 64;

        // load K,V tiles
#pragma unroll
        for (int it = 0; it < 4; it++) {
            const int i  = tid + it * 256;
            const int r  = i >> 4;
            const int c4 = (i & 15) << 2;
            const size_t off = (size_t)(k0 + r) * 3072 + c4;
            *(float4*)&Ks[r * PIT + c4] = *(const float4*)(kb + off);
            *(float4*)&Vs[r * PIT + c4] = *(const float4*)(vb + off);
        }
        __syncthreads();

        // S = Q @ K^T (4x4 per thread)
        float s[4][4];
#pragma unroll
        for (int i = 0; i < 4; i++)
#pragma unroll
            for (int j = 0; j < 4; j++) s[i][j] = 0.f;

#pragma unroll 4
        for (int d4 = 0; d4 < 64; d4 += 4) {
            float4 qv[4], kv[4];
#pragma unroll
            for (int i = 0; i < 4; i++)
                qv[i] = *(const float4*)&Qs[(ty * 4 + i) * PIT + d4];
#pragma unroll
            for (int j = 0; j < 4; j++)
                kv[j] = *(const float4*)&Ks[(tx + 16 * j) * PIT + d4];
#pragma unroll
            for (int i = 0; i < 4; i++)
#pragma unroll
                for (int j = 0; j < 4; j++) {
                    s[i][j] = fmaf(qv[i].x, kv[j].x, s[i][j]);
                    s[i][j] = fmaf(qv[i].y, kv[j].y, s[i][j]);
                    s[i][j] = fmaf(qv[i].z, kv[j].z, s[i][j]);
                    s[i][j] = fmaf(qv[i].w, kv[j].w, s[i][j]);
                }
        }

        // scale + causal mask (only the diagonal tile can be masked)
        if (kt == qt) {
#pragma unroll
            for (int i = 0; i < 4; i++)
#pragma unroll
                for (int j = 0; j < 4; j++) {
                    const int c = tx + 16 * j;
                    const int r = ty * 4 + i;
                    s[i][j] = (c > r) ? -1.0e30f : s[i][j] * 0.125f;
                }
        } else {
#pragma unroll
            for (int i = 0; i < 4; i++)
#pragma unroll
                for (int j = 0; j < 4; j++) s[i][j] *= 0.125f;
        }

        // online softmax: row max across the 16-lane row group
        float tm[4], rs[4], corr[4];
#pragma unroll
        for (int i = 0; i < 4; i++)
            tm[i] = fmaxf(fmaxf(s[i][0], s[i][1]), fmaxf(s[i][2], s[i][3]));
#pragma unroll
        for (int o = 1; o < 16; o <<= 1)
#pragma unroll
            for (int i = 0; i < 4; i++)
                tm[i] = fmaxf(tm[i], __shfl_xor_sync(0xffffffffu, tm[i], o));
#pragma unroll
        for (int i = 0; i < 4; i++) {
            const float nm = fmaxf(mrow[i], tm[i]);
            corr[i] = __expf(mrow[i] - nm);
            mrow[i] = nm;
        }
#pragma unroll
        for (int i = 0; i < 4; i++) {
            float su = 0.f;
#pragma unroll
            for (int j = 0; j < 4; j++) {
                s[i][j] = __expf(s[i][j] - mrow[i]);   // masked -> exp(-1e30)=0
                su += s[i][j];
            }
            rs[i] = su;
        }
#pragma unroll
        for (int o = 1; o < 16; o <<= 1)
#pragma unroll
            for (int i = 0; i < 4; i++)
                rs[i] += __shfl_xor_sync(0xffffffffu, rs[i], o);
#pragma unroll
        for (int i = 0; i < 4; i++) {
            lrow[i] = lrow[i] * corr[i] + rs[i];
#pragma unroll
            for (int j = 0; j < 4; j++) O[i][j] *= corr[i];
        }

        // stash P to smem, then O += P @ V
#pragma unroll
        for (int i = 0; i < 4; i++)
#pragma unroll
            for (int j = 0; j < 4; j++)
                Ps[(ty * 4 + i) * PIT + tx + 16 * j] = s[i][j];
        __syncthreads();

#pragma unroll 4
        for (int j2 = 0; j2 < 64; j2++) {
            float pv[4], vv[4];
#pragma unroll
            for (int i = 0; i < 4; i++) pv[i] = Ps[(ty * 4 + i) * PIT + j2];
#pragma unroll
            for (int c = 0; c < 4; c++) vv[c] = Vs[j2 * PIT + tx + 16 * c];
#pragma unroll
            for (int i = 0; i < 4; i++)
#pragma unroll
                for (int c = 0; c < 4; c++)
                    O[i][c] = fmaf(pv[i], vv[c], O[i][c]);
        }
        __syncthreads();
    }

    // normalize + write ctx in merged-head layout [B*S, 1024]
#pragma unroll
    for (int i = 0; i < 4; i++) {
        const float inv = 1.0f / lrow[i];
        const size_t rowoff =
            (size_t)(b * 2048 + q0 + ty * 4 + i) * 1024 + h * 64;
#pragma unroll
        for (int c = 0; c < 4; c++)
            ctx[rowoff + tx + 16 * c] = O[i][c] * inv;
    }
}

// ---------------------------------------------------------------------------
// launch
// ---------------------------------------------------------------------------
extern "C" void kernel_launch(void* const* d_in, const int* in_sizes, int n_in,
                              void* d_out, int out_size)
{
    (void)in_sizes; (void)n_in; (void)out_size;
    const float* x     = (const float*)d_in[0];
    const float* Wqkv  = (const float*)d_in[1];
    const float* bqkv  = (const float*)d_in[2];
    const float* Alora = (const float*)d_in[3];
    const float* Blora = (const float*)d_in[4];
    const float* Wproj = (const float*)d_in[5];
    const float* bproj = (const float*)d_in[6];
    float* out = (float*)d_out;

    float *xa = nullptr, *qkv = nullptr, *ctx = nullptr;
    cudaGetSymbolAddress((void**)&xa,  g_xa);
    cudaGetSymbolAddress((void**)&qkv, g_qkv);
    cudaGetSymbolAddress((void**)&ctx, g_ctx);

    // 1) LoRA down-projection
    xa_kernel<<<4096, 128>>>(x, Alora, xa);

    // 2) qkv = x @ Wqkv + b + ALPHA * (xa @ Blora)
    sgemm128<true><<<dim3(3072 / 128, 4096 / 128), 256>>>(
        x, Wqkv, bqkv, xa, Blora, qkv, 4096, 3072, 1024);

    // 3) causal flash attention -> merged-head ctx
    const int flash_smem = 4 * 64 * 68 * (int)sizeof(float);
    cudaFuncSetAttribute(flash_kernel,
                         cudaFuncAttributeMaxDynamicSharedMemorySize,
                         flash_smem);
    flash_kernel<<<dim3(2048 / 64, 16, 2), 256, flash_smem>>>(qkv, ctx);

    // 4) out = ctx @ Wproj + b_proj
    sgemm128<false><<<dim3(1024 / 128, 4096 / 128), 256>>>(
        ctx, Wproj, bproj, nullptr, nullptr, out, 4096, 1024, 1024);
}

// round 3
// speedup vs baseline: 1.4466x; 1.4466x over previous
#include <cuda_runtime.h>
#include <cuda_bf16.h>
#include <cstdint>

// ---------------------------------------------------------------------------
// B=2, S=2048, D=1024, H=16, HD=64, RANK=8, ALPHA=8
// ---------------------------------------------------------------------------

__device__ __align__(256) float g_xa [4096 * 8];
__device__ __align__(256) float g_qkv[4096 * 3072];
__device__ __align__(256) float g_ctx[4096 * 1024];
__device__ __align__(256) __nv_bfloat16 g_xh [4096 * 1024];
__device__ __align__(256) __nv_bfloat16 g_xl [4096 * 1024];
__device__ __align__(256) __nv_bfloat16 g_wqh[3072 * 1024];
__device__ __align__(256) __nv_bfloat16 g_wql[3072 * 1024];
__device__ __align__(256) __nv_bfloat16 g_wph[1024 * 1024];
__device__ __align__(256) __nv_bfloat16 g_wpl[1024 * 1024];
__device__ __align__(256) __nv_bfloat16 g_ch [4096 * 1024];
__device__ __align__(256) __nv_bfloat16 g_cl [4096 * 1024];

// ------------------------------ asm helpers --------------------------------
__device__ __forceinline__ uint32_t smem_u32(const void* p) {
    uint32_t a;
    asm("{ .reg .u64 t; cvta.to.shared.u64 t, %1; cvt.u32.u64 %0, t; }"
        : "=r"(a) : "l"(p));
    return a;
}
#define LDSM_X4(r0, r1, r2, r3, addr)                                     \
    asm volatile("ldmatrix.sync.aligned.m8n8.x4.shared.b16 "              \
                 "{%0,%1,%2,%3}, [%4];"                                   \
                 : "=r"(r0), "=r"(r1), "=r"(r2), "=r"(r3) : "r"(addr))
#define CP_ASYNC16(dst, src)                                              \
    asm volatile("cp.async.cg.shared.global [%0], [%1], 16;"              \
                 :: "r"(dst), "l"(src))
#define CP_COMMIT()  asm volatile("cp.async.commit_group;")
#define CP_WAIT(n)   asm volatile("cp.async.wait_group %0;" :: "n"(n))

__device__ __forceinline__ void mma16816(float* c,
                                         uint32_t a0, uint32_t a1,
                                         uint32_t a2, uint32_t a3,
                                         uint32_t b0, uint32_t b1)
{
    asm volatile(
        "mma.sync.aligned.m16n8k16.row.col.f32.bf16.bf16.f32 "
        "{%0,%1,%2,%3}, {%4,%5,%6,%7}, {%8,%9}, {%0,%1,%2,%3};"
        : "+f"(c[0]), "+f"(c[1]), "+f"(c[2]), "+f"(c[3])
        : "r"(a0), "r"(a1), "r"(a2), "r"(a3), "r"(b0), "r"(b1));
}

// ---------------------------------------------------------------------------
// prep: fp32 -> bf16 hi/lo split
// ---------------------------------------------------------------------------
__global__ __launch_bounds__(256) void split_bf16(const float4* __restrict__ x,
                                                  __nv_bfloat162* __restrict__ h,
                                                  __nv_bfloat162* __restrict__ l,
                                                  int n4)
{
    int i = blockIdx.x * blockDim.x + threadIdx.x;
    if (i >= n4) return;
    float4 v = x[i];
    __nv_bfloat16 h0 = __float2bfloat16(v.x);
    __nv_bfloat16 h1 = __float2bfloat16(v.y);
    __nv_bfloat16 h2 = __float2bfloat16(v.z);
    __nv_bfloat16 h3 = __float2bfloat16(v.w);
    __nv_bfloat162 a, b, c, d;
    a.x = h0; a.y = h1; b.x = h2; b.y = h3;
    c.x = __float2bfloat16(v.x - __bfloat162float(h0));
    c.y = __float2bfloat16(v.y - __bfloat162float(h1));
    d.x = __float2bfloat16(v.z - __bfloat162float(h2));
    d.y = __float2bfloat16(v.w - __bfloat162float(h3));
    h[2 * i] = a; h[2 * i + 1] = b;
    l[2 * i] = c; l[2 * i + 1] = d;
}

// ---------------------------------------------------------------------------
// prep: W[K,N] fp32 -> Th/Tl[N,K] bf16 (transpose + split)
// ---------------------------------------------------------------------------
__global__ __launch_bounds__(256) void transpose_split(const float* __restrict__ W,
                                                       __nv_bfloat16* __restrict__ Th,
                                                       __nv_bfloat16* __restrict__ Tl,
                                                       int K, int N)
{
    __shared__ float t[32][33];
    const int n0 = blockIdx.x * 32, k0 = blockIdx.y * 32;
#pragma unroll
    for (int i = threadIdx.y; i < 32; i += 8)
        t[i][threadIdx.x] = W[(size_t)(k0 + i) * N + n0 + threadIdx.x];
    __syncthreads();
#pragma unroll
    for (int i = threadIdx.y; i < 32; i += 8) {
        float v = t[threadIdx.x][i];
        __nv_bfloat16 hh = __float2bfloat16(v);
        Th[(size_t)(n0 + i) * K + k0 + threadIdx.x] = hh;
        Tl[(size_t)(n0 + i) * K + k0 + threadIdx.x] =
            __float2bfloat16(v - __bfloat162float(hh));
    }
}

// ---------------------------------------------------------------------------
// xa = x @ A_lora
// ---------------------------------------------------------------------------
__global__ __launch_bounds__(128) void xa_kernel(const float* __restrict__ x,
                                                 const float* __restrict__ Al,
                                                 float* __restrict__ xa)
{
    const int m = blockIdx.x, tid = threadIdx.x;
    float acc[8];
#pragma unroll
    for (int r = 0; r < 8; r++) acc[r] = 0.f;
    const float* xr = x + (size_t)m * 1024;
    for (int k = tid; k < 1024; k += 128) {
        const float xv = xr[k];
        const float4 a0 = *(const float4*)(Al + (size_t)k * 8);
        const float4 a1 = *(const float4*)(Al + (size_t)k * 8 + 4);
        acc[0] = fmaf(xv, a0.x, acc[0]); acc[1] = fmaf(xv, a0.y, acc[1]);
        acc[2] = fmaf(xv, a0.z, acc[2]); acc[3] = fmaf(xv, a0.w, acc[3]);
        acc[4] = fmaf(xv, a1.x, acc[4]); acc[5] = fmaf(xv, a1.y, acc[5]);
        acc[6] = fmaf(xv, a1.z, acc[6]); acc[7] = fmaf(xv, a1.w, acc[7]);
    }
#pragma unroll
    for (int off = 16; off > 0; off >>= 1)
#pragma unroll
        for (int r = 0; r < 8; r++)
            acc[r] += __shfl_xor_sync(0xffffffffu, acc[r], off);
    __shared__ float red[4][8];
    if ((tid & 31) == 0)
#pragma unroll
        for (int r = 0; r < 8; r++) red[tid >> 5][r] = acc[r];
    __syncthreads();
    if (tid < 8)
        xa[(size_t)m * 8 + tid] = red[0][tid] + red[1][tid] + red[2][tid] + red[3][tid];
}

// ---------------------------------------------------------------------------
// HMMA GEMM:  C[M,N] = (Ah+Al)[M,K] @ (Bh+Bl)[N,K]^T + bias (+LoRA)
// block tile 128x128x32; SMEM tiles [128][40] bf16 (80B pitch); cp.async
// double buffered. 8 warps = 2(M) x 4(N); warp tile 64x32; m16n8k16.
// ---------------------------------------------------------------------------
static constexpr int TPITCH = 80;                  // bytes per smem tile row
static constexpr int TILE_B = 128 * TPITCH;        // 10240 B
static constexpr int BUF_B  = 4 * TILE_B;          // Ah,Al,Bh,Bl

__device__ __forceinline__ void ldtile_async(uint32_t sdst,
                                             const __nv_bfloat16* __restrict__ g,
                                             int row0, int k0, int ldk, int tid)
{
#pragma unroll
    for (int it = 0; it < 2; it++) {
        const int idx = tid + it * 256;
        const int r = idx >> 2, c = idx & 3;
        CP_ASYNC16(sdst + r * TPITCH + c * 16,
                   g + (size_t)(row0 + r) * ldk + k0 + c * 8);
    }
}

template<bool LORA>
__global__ __launch_bounds__(256, 1) void gemm_mma(
    const __nv_bfloat16* __restrict__ Ah, const __nv_bfloat16* __restrict__ Al,
    const __nv_bfloat16* __restrict__ Bh, const __nv_bfloat16* __restrict__ Bl,
    const float* __restrict__ bias,
    const float* __restrict__ xa, const float* __restrict__ BlLora,
    float* __restrict__ C, int M, int N, int K)
{
    extern __shared__ char smem[];
    const uint32_t sb = smem_u32(smem);
    const int tid = threadIdx.x;
    const int warp = tid >> 5, lane = tid & 31;
    const int wm = warp & 1, wn = warp >> 1;
    const int bn = blockIdx.x, bm = blockIdx.y;

    float acc[4][4][4];
#pragma unroll
    for (int mi = 0; mi < 4; mi++)
#pragma unroll
        for (int ni = 0; ni < 4; ni++)
#pragma unroll
            for (int e = 0; e < 4; e++) acc[mi][ni][e] = 0.f;

    const int nit = K >> 5;

    // prologue: load chunk 0 into buffer 0
    {
        const uint32_t s0 = sb;
        ldtile_async(s0,              Ah, bm * 128, 0, K, tid);
        ldtile_async(s0 + TILE_B,     Al, bm * 128, 0, K, tid);
        ldtile_async(s0 + 2 * TILE_B, Bh, bn * 128, 0, K, tid);
        ldtile_async(s0 + 3 * TILE_B, Bl, bn * 128, 0, K, tid);
        CP_COMMIT();
    }

    // per-lane ldmatrix row-address component (bytes)
    const uint32_t lrow = (uint32_t)(lane & 15) * TPITCH + (uint32_t)(lane >> 4) * 16;

    for (int it = 0; it < nit; it++) {
        if (it + 1 < nit) {
            const uint32_t s1 = sb + ((it + 1) & 1) * BUF_B;
            const int k1 = (it + 1) * 32;
            ldtile_async(s1,              Ah, bm * 128, k1, K, tid);
            ldtile_async(s1 + TILE_B,     Al, bm * 128, k1, K, tid);
            ldtile_async(s1 + 2 * TILE_B, Bh, bn * 128, k1, K, tid);
            ldtile_async(s1 + 3 * TILE_B, Bl, bn * 128, k1, K, tid);
            CP_COMMIT();
            CP_WAIT(1);
        } else {
            CP_WAIT(0);
        }
        __syncthreads();

        const uint32_t s0 = sb + (it & 1) * BUF_B;
        const uint32_t aBase = s0 + (wm * 64) * TPITCH + lrow;
        const uint32_t bBase = s0 + 2 * TILE_B + (wn * 32) * TPITCH + lrow;

#pragma unroll
        for (int kk = 0; kk < 2; kk++) {
            const uint32_t kOff = kk * 32;   // 16 bf16 = 32 bytes
            uint32_t ah[4][4], al[4][4], bh[4][2], bl[4][2];
#pragma unroll
            for (int mi = 0; mi < 4; mi++) {
                LDSM_X4(ah[mi][0], ah[mi][1], ah[mi][2], ah[mi][3],
                        aBase + mi * 16 * TPITCH + kOff);
                LDSM_X4(al[mi][0], al[mi][1], al[mi][2], al[mi][3],
                        aBase + TILE_B + mi * 16 * TPITCH + kOff);
            }
#pragma unroll
            for (int n2 = 0; n2 < 2; n2++) {
                uint32_t r0, r1, r2, r3;
                LDSM_X4(r0, r1, r2, r3, bBase + n2 * 16 * TPITCH + kOff);
                bh[n2 * 2][0] = r0; bh[n2 * 2][1] = r2;
                bh[n2 * 2 + 1][0] = r1; bh[n2 * 2 + 1][1] = r3;
                LDSM_X4(r0, r1, r2, r3, bBase + TILE_B + n2 * 16 * TPITCH + kOff);
                bl[n2 * 2][0] = r0; bl[n2 * 2][1] = r2;
                bl[n2 * 2 + 1][0] = r1; bl[n2 * 2 + 1][1] = r3;
            }
#pragma unroll
            for (int mi = 0; mi < 4; mi++)
#pragma unroll
                for (int ni = 0; ni < 4; ni++) {
                    mma16816(acc[mi][ni], ah[mi][0], ah[mi][1], ah[mi][2], ah[mi][3],
                             bh[ni][0], bh[ni][1]);
                    mma16816(acc[mi][ni], ah[mi][0], ah[mi][1], ah[mi][2], ah[mi][3],
                             bl[ni][0], bl[ni][1]);
                    mma16816(acc[mi][ni], al[mi][0], al[mi][1], al[mi][2], al[mi][3],
                             bh[ni][0], bh[ni][1]);
                }
        }
        __syncthreads();
    }

    // epilogue: stage LoRA operands to smem (buffers are free now)
    float* blsm = (float*)smem;            // [8][128], ALPHA folded
    float* xasm = blsm + 1024;             // [128][8]
    if (LORA) {
#pragma unroll
        for (int i = tid; i < 1024; i += 256) {
            blsm[i] = BlLora[(size_t)(i >> 7) * N + bn * 128 + (i & 127)] * 8.0f;
            xasm[i] = xa[(size_t)(bm * 128) * 8 + i];
        }
        __syncthreads();
    }

    const int g = lane >> 2, tig = lane & 3;
#pragma unroll
    for (int mi = 0; mi < 4; mi++) {
#pragma unroll
        for (int half = 0; half < 2; half++) {
            const int rloc = wm * 64 + mi * 16 + g + half * 8;
            const int grow = bm * 128 + rloc;
            float xv[8];
            if (LORA) {
#pragma unroll
                for (int r = 0; r < 8; r++) xv[r] = xasm[rloc * 8 + r];
            }
            float* crow = C + (size_t)grow * N + bn * 128;
#pragma unroll
            for (int ni = 0; ni < 4; ni++) {
                const int cloc = wn * 32 + ni * 8 + tig * 2;
                float v0 = acc[mi][ni][half * 2 + 0] + bias[bn * 128 + cloc];
                float v1 = acc[mi][ni][half * 2 + 1] + bias[bn * 128 + cloc + 1];
                if (LORA) {
#pragma unroll
                    for (int r = 0; r < 8; r++) {
                        v0 = fmaf(xv[r], blsm[r * 128 + cloc],     v0);
                        v1 = fmaf(xv[r], blsm[r * 128 + cloc + 1], v1);
                    }
                }
                float2 o; o.x = v0; o.y = v1;
                *(float2*)(crow + cloc) = o;
            }
        }
    }
}

// ---------------------------------------------------------------------------
// Causal flash attention, fp32 (unchanged)
// ---------------------------------------------------------------------------
__global__ __launch_bounds__(256) void flash_kernel(const float* __restrict__ qkv,
                                                    float* __restrict__ ctx)
{
    extern __shared__ float sm[];
    const int PIT = 68;
    float* Qs = sm;
    float* Ks = sm + 64 * PIT;
    float* Vs = sm + 2 * 64 * PIT;
    float* Ps = sm + 3 * 64 * PIT;

    const int tid = threadIdx.x;
    const int tx = tid & 15, ty = tid >> 4;
    const int qt = blockIdx.x, h = blockIdx.y, b = blockIdx.z;
    const int q0 = qt * 64;

    const float* qb = qkv + (size_t)b * 2048 * 3072 + h * 64;
    const float* kb = qb + 1024;
    const float* vb = qb + 2048;

#pragma unroll
    for (int it = 0; it < 4; it++) {
        const int i = tid + it * 256;
        const int r = i >> 4, c4 = (i & 15) << 2;
        *(float4*)&Qs[r * PIT + c4] = *(const float4*)(qb + (size_t)(q0 + r) * 3072 + c4);
    }

    float O[4][4], mrow[4], lrow[4];
#pragma unroll
    for (int i = 0; i < 4; i++) {
        mrow[i] = -3.0e38f; lrow[i] = 0.f;
#pragma unroll
        for (int j = 0; j < 4; j++) O[i][j] = 0.f;
    }
    __syncthreads();

    for (int kt = 0; kt <= qt; kt++) {
        const int k0 = kt * 64;
#pragma unroll
        for (int it = 0; it < 4; it++) {
            const int i = tid + it * 256;
            const int r = i >> 4, c4 = (i & 15) << 2;
            const size_t off = (size_t)(k0 + r) * 3072 + c4;
            *(float4*)&Ks[r * PIT + c4] = *(const float4*)(kb + off);
            *(float4*)&Vs[r * PIT + c4] = *(const float4*)(vb + off);
        }
        __syncthreads();

        float s[4][4];
#pragma unroll
        for (int i = 0; i < 4; i++)
#pragma unroll
            for (int j = 0; j < 4; j++) s[i][j] = 0.f;

#pragma unroll 4
        for (int d4 = 0; d4 < 64; d4 += 4) {
            float4 qv[4], kv[4];
#pragma unroll
            for (int i = 0; i < 4; i++) qv[i] = *(const float4*)&Qs[(ty * 4 + i) * PIT + d4];
#pragma unroll
            for (int j = 0; j < 4; j++) kv[j] = *(const float4*)&Ks[(tx + 16 * j) * PIT + d4];
#pragma unroll
            for (int i = 0; i < 4; i++)
#pragma unroll
                for (int j = 0; j < 4; j++) {
                    s[i][j] = fmaf(qv[i].x, kv[j].x, s[i][j]);
                    s[i][j] = fmaf(qv[i].y, kv[j].y, s[i][j]);
                    s[i][j] = fmaf(qv[i].z, kv[j].z, s[i][j]);
                    s[i][j] = fmaf(qv[i].w, kv[j].w, s[i][j]);
                }
        }

        if (kt == qt) {
#pragma unroll
            for (int i = 0; i < 4; i++)
#pragma unroll
                for (int j = 0; j < 4; j++) {
                    const int c = tx + 16 * j, r = ty * 4 + i;
                    s[i][j] = (c > r) ? -1.0e30f : s[i][j] * 0.125f;
                }
        } else {
#pragma unroll
            for (int i = 0; i < 4; i++)
#pragma unroll
                for (int j = 0; j < 4; j++) s[i][j] *= 0.125f;
        }

        float tm[4], rs[4], corr[4];
#pragma unroll
        for (int i = 0; i < 4; i++)
            tm[i] = fmaxf(fmaxf(s[i][0], s[i][1]), fmaxf(s[i][2], s[i][3]));
#pragma unroll
        for (int o = 1; o < 16; o <<= 1)
#pragma unroll
            for (int i = 0; i < 4; i++)
                tm[i] = fmaxf(tm[i], __shfl_xor_sync(0xffffffffu, tm[i], o));
#pragma unroll
        for (int i = 0; i < 4; i++) {
            const float nm = fmaxf(mrow[i], tm[i]);
            corr[i] = __expf(mrow[i] - nm);
            mrow[i] = nm;
        }
#pragma unroll
        for (int i = 0; i < 4; i++) {
            float su = 0.f;
#pragma unroll
            for (int j = 0; j < 4; j++) { s[i][j] = __expf(s[i][j] - mrow[i]); su += s[i][j]; }
            rs[i] = su;
        }
#pragma unroll
        for (int o = 1; o < 16; o <<= 1)
#pragma unroll
            for (int i = 0; i < 4; i++)
                rs[i] += __shfl_xor_sync(0xffffffffu, rs[i], o);
#pragma unroll
        for (int i = 0; i < 4; i++) {
            lrow[i] = lrow[i] * corr[i] + rs[i];
#pragma unroll
            for (int j = 0; j < 4; j++) O[i][j] *= corr[i];
        }

#pragma unroll
        for (int i = 0; i < 4; i++)
#pragma unroll
            for (int j = 0; j < 4; j++)
                Ps[(ty * 4 + i) * PIT + tx + 16 * j] = s[i][j];
        __syncthreads();

#pragma unroll 4
        for (int j2 = 0; j2 < 64; j2++) {
            float pv[4], vv[4];
#pragma unroll
            for (int i = 0; i < 4; i++) pv[i] = Ps[(ty * 4 + i) * PIT + j2];
#pragma unroll
            for (int c = 0; c < 4; c++) vv[c] = Vs[j2 * PIT + tx + 16 * c];
#pragma unroll
            for (int i = 0; i < 4; i++)
#pragma unroll
                for (int c = 0; c < 4; c++)
                    O[i][c] = fmaf(pv[i], vv[c], O[i][c]);
        }
        __syncthreads();
    }

#pragma unroll
    for (int i = 0; i < 4; i++) {
        const float inv = 1.0f / lrow[i];
        const size_t rowoff = (size_t)(b * 2048 + q0 + ty * 4 + i) * 1024 + h * 64;
#pragma unroll
        for (int c = 0; c < 4; c++)
            ctx[rowoff + tx + 16 * c] = O[i][c] * inv;
    }
}

// ---------------------------------------------------------------------------
// launch
// ---------------------------------------------------------------------------
extern "C" void kernel_launch(void* const* d_in, const int* in_sizes, int n_in,
                              void* d_out, int out_size)
{
    (void)in_sizes; (void)n_in; (void)out_size;
    const float* x     = (const float*)d_in[0];
    const float* Wqkv  = (const float*)d_in[1];
    const float* bqkv  = (const float*)d_in[2];
    const float* Alora = (const float*)d_in[3];
    const float* Blora = (const float*)d_in[4];
    const float* Wproj = (const float*)d_in[5];
    const float* bproj = (const float*)d_in[6];
    float* out = (float*)d_out;

    float *xa, *qkv, *ctx;
    __nv_bfloat16 *xh, *xl, *wqh, *wql, *wph, *wpl, *ch, *cl;
    cudaGetSymbolAddress((void**)&xa,  g_xa);
    cudaGetSymbolAddress((void**)&qkv, g_qkv);
    cudaGetSymbolAddress((void**)&ctx, g_ctx);
    cudaGetSymbolAddress((void**)&xh,  g_xh);
    cudaGetSymbolAddress((void**)&xl,  g_xl);
    cudaGetSymbolAddress((void**)&wqh, g_wqh);
    cudaGetSymbolAddress((void**)&wql, g_wql);
    cudaGetSymbolAddress((void**)&wph, g_wph);
    cudaGetSymbolAddress((void**)&wpl, g_wpl);
    cudaGetSymbolAddress((void**)&ch,  g_ch);
    cudaGetSymbolAddress((void**)&cl,  g_cl);

    const int gemm_smem = 2 * BUF_B;   // 81920 B
    cudaFuncSetAttribute(gemm_mma<true>,  cudaFuncAttributeMaxDynamicSharedMemorySize, gemm_smem);
    cudaFuncSetAttribute(gemm_mma<false>, cudaFuncAttributeMaxDynamicSharedMemorySize, gemm_smem);
    const int flash_smem = 4 * 64 * 68 * (int)sizeof(float);
    cudaFuncSetAttribute(flash_kernel, cudaFuncAttributeMaxDynamicSharedMemorySize, flash_smem);

    // prep
    split_bf16<<<4096, 256>>>((const float4*)x, (__nv_bfloat162*)xh, (__nv_bfloat162*)xl,
                              4096 * 1024 / 4);
    transpose_split<<<dim3(96, 32), dim3(32, 8)>>>(Wqkv, wqh, wql, 1024, 3072);
    transpose_split<<<dim3(32, 32), dim3(32, 8)>>>(Wproj, wph, wpl, 1024, 1024);
    xa_kernel<<<4096, 128>>>(x, Alora, xa);

    // qkv = x @ Wqkv + b + ALPHA * (xa @ Blora)
    gemm_mma<true><<<dim3(24, 32), 256, gemm_smem>>>(
        xh, xl, wqh, wql, bqkv, xa, Blora, qkv, 4096, 3072, 1024);

    // attention
    flash_kernel<<<dim3(32, 16, 2), 256, flash_smem>>>(qkv, ctx);

    // split ctx, then out = ctx @ Wproj + b
    split_bf16<<<4096, 256>>>((const float4*)ctx, (__nv_bfloat162*)ch, (__nv_bfloat162*)cl,
                              4096 * 1024 / 4);
    gemm_mma<false><<<dim3(8, 32), 256, gemm_smem>>>(
        ch, cl, wph, wpl, bproj, nullptr, nullptr, out, 4096, 1024, 1024);
}

// round 4
// speedup vs baseline: 2.3204x; 1.6040x over previous
#include <cuda_runtime.h>
#include <cuda_bf16.h>
#include <cstdint>

// ---------------------------------------------------------------------------
// B=2, S=2048, D=1024, H=16, HD=64, RANK=8, ALPHA=8
// qkv split arrays: [4096][3072] bf16 hi/lo.  ctx split: [4096][1024] hi/lo.
// ---------------------------------------------------------------------------

__device__ __align__(256) float g_xa [4096 * 8];
__device__ __align__(256) __nv_bfloat16 g_xh [4096 * 1024];
__device__ __align__(256) __nv_bfloat16 g_xl [4096 * 1024];
__device__ __align__(256) __nv_bfloat16 g_wqh[3072 * 1024];
__device__ __align__(256) __nv_bfloat16 g_wql[3072 * 1024];
__device__ __align__(256) __nv_bfloat16 g_wph[1024 * 1024];
__device__ __align__(256) __nv_bfloat16 g_wpl[1024 * 1024];
__device__ __align__(256) __nv_bfloat16 g_qh [4096 * 3072];
__device__ __align__(256) __nv_bfloat16 g_ql [4096 * 3072];
__device__ __align__(256) __nv_bfloat16 g_ch [4096 * 1024];
__device__ __align__(256) __nv_bfloat16 g_cl [4096 * 1024];

// ------------------------------ asm helpers --------------------------------
__device__ __forceinline__ uint32_t smem_u32(const void* p) {
    uint32_t a;
    asm("{ .reg .u64 t; cvta.to.shared.u64 t, %1; cvt.u32.u64 %0, t; }"
        : "=r"(a) : "l"(p));
    return a;
}
#define LDSM_X4(r0, r1, r2, r3, addr)                                     \
    asm volatile("ldmatrix.sync.aligned.m8n8.x4.shared.b16 "              \
                 "{%0,%1,%2,%3}, [%4];"                                   \
                 : "=r"(r0), "=r"(r1), "=r"(r2), "=r"(r3) : "r"(addr))
#define LDSM_X4_T(r0, r1, r2, r3, addr)                                   \
    asm volatile("ldmatrix.sync.aligned.m8n8.x4.trans.shared.b16 "        \
                 "{%0,%1,%2,%3}, [%4];"                                   \
                 : "=r"(r0), "=r"(r1), "=r"(r2), "=r"(r3) : "r"(addr))
#define CP_ASYNC16(dst, src)                                              \
    asm volatile("cp.async.cg.shared.global [%0], [%1], 16;"              \
                 :: "r"(dst), "l"(src))
#define CP_COMMIT()  asm volatile("cp.async.commit_group;")
#define CP_WAIT(n)   asm volatile("cp.async.wait_group %0;" :: "n"(n))

__device__ __forceinline__ void mma16816(float* c,
                                         uint32_t a0, uint32_t a1,
                                         uint32_t a2, uint32_t a3,
                                         uint32_t b0, uint32_t b1)
{
    asm volatile(
        "mma.sync.aligned.m16n8k16.row.col.f32.bf16.bf16.f32 "
        "{%0,%1,%2,%3}, {%4,%5,%6,%7}, {%8,%9}, {%0,%1,%2,%3};"
        : "+f"(c[0]), "+f"(c[1]), "+f"(c[2]), "+f"(c[3])
        : "r"(a0), "r"(a1), "r"(a2), "r"(a3), "r"(b0), "r"(b1));
}

// split two fp32 into packed bf16x2 hi + lo
__device__ __forceinline__ void split2(float x, float y, uint32_t& h, uint32_t& l)
{
    __nv_bfloat16 hx = __float2bfloat16(x);
    __nv_bfloat16 hy = __float2bfloat16(y);
    __nv_bfloat16 lx = __float2bfloat16(x - __bfloat162float(hx));
    __nv_bfloat16 ly = __float2bfloat16(y - __bfloat162float(hy));
    __nv_bfloat162 hp, lp;
    hp.x = hx; hp.y = hy;
    lp.x = lx; lp.y = ly;
    h = *(uint32_t*)&hp;
    l = *(uint32_t*)&lp;
}

// ---------------------------------------------------------------------------
// prep: fp32 -> bf16 hi/lo split (x only)
// ---------------------------------------------------------------------------
__global__ __launch_bounds__(256) void split_bf16(const float4* __restrict__ x,
                                                  __nv_bfloat162* __restrict__ h,
                                                  __nv_bfloat162* __restrict__ l,
                                                  int n4)
{
    int i = blockIdx.x * blockDim.x + threadIdx.x;
    if (i >= n4) return;
    float4 v = x[i];
    uint32_t h0, l0, h1, l1;
    split2(v.x, v.y, h0, l0);
    split2(v.z, v.w, h1, l1);
    h[2 * i]     = *(__nv_bfloat162*)&h0;
    h[2 * i + 1] = *(__nv_bfloat162*)&h1;
    l[2 * i]     = *(__nv_bfloat162*)&l0;
    l[2 * i + 1] = *(__nv_bfloat162*)&l1;
}

// ---------------------------------------------------------------------------
// prep: W[K,N] fp32 -> Th/Tl[N,K] bf16 (transpose + split)
// ---------------------------------------------------------------------------
__global__ __launch_bounds__(256) void transpose_split(const float* __restrict__ W,
                                                       __nv_bfloat16* __restrict__ Th,
                                                       __nv_bfloat16* __restrict__ Tl,
                                                       int K, int N)
{
    __shared__ float t[32][33];
    const int n0 = blockIdx.x * 32, k0 = blockIdx.y * 32;
#pragma unroll
    for (int i = threadIdx.y; i < 32; i += 8)
        t[i][threadIdx.x] = W[(size_t)(k0 + i) * N + n0 + threadIdx.x];
    __syncthreads();
#pragma unroll
    for (int i = threadIdx.y; i < 32; i += 8) {
        float v = t[threadIdx.x][i];
        __nv_bfloat16 hh = __float2bfloat16(v);
        Th[(size_t)(n0 + i) * K + k0 + threadIdx.x] = hh;
        Tl[(size_t)(n0 + i) * K + k0 + threadIdx.x] =
            __float2bfloat16(v - __bfloat162float(hh));
    }
}

// ---------------------------------------------------------------------------
// xa = x @ A_lora
// ---------------------------------------------------------------------------
__global__ __launch_bounds__(128) void xa_kernel(const float* __restrict__ x,
                                                 const float* __restrict__ Al,
                                                 float* __restrict__ xa)
{
    const int m = blockIdx.x, tid = threadIdx.x;
    float acc[8];
#pragma unroll
    for (int r = 0; r < 8; r++) acc[r] = 0.f;
    const float* xr = x + (size_t)m * 1024;
    for (int k = tid; k < 1024; k += 128) {
        const float xv = xr[k];
        const float4 a0 = *(const float4*)(Al + (size_t)k * 8);
        const float4 a1 = *(const float4*)(Al + (size_t)k * 8 + 4);
        acc[0] = fmaf(xv, a0.x, acc[0]); acc[1] = fmaf(xv, a0.y, acc[1]);
        acc[2] = fmaf(xv, a0.z, acc[2]); acc[3] = fmaf(xv, a0.w, acc[3]);
        acc[4] = fmaf(xv, a1.x, acc[4]); acc[5] = fmaf(xv, a1.y, acc[5]);
        acc[6] = fmaf(xv, a1.z, acc[6]); acc[7] = fmaf(xv, a1.w, acc[7]);
    }
#pragma unroll
    for (int off = 16; off > 0; off >>= 1)
#pragma unroll
        for (int r = 0; r < 8; r++)
            acc[r] += __shfl_xor_sync(0xffffffffu, acc[r], off);
    __shared__ float red[4][8];
    if ((tid & 31) == 0)
#pragma unroll
        for (int r = 0; r < 8; r++) red[tid >> 5][r] = acc[r];
    __syncthreads();
    if (tid < 8)
        xa[(size_t)m * 8 + tid] = red[0][tid] + red[1][tid] + red[2][tid] + red[3][tid];
}

// ---------------------------------------------------------------------------
// HMMA GEMM:  C[M,N] = (Ah+Al)[M,K] @ (Bh+Bl)[N,K]^T + bias (+LoRA)
// SPLITOUT: write bf16 hi/lo pair arrays instead of fp32.
// ---------------------------------------------------------------------------
static constexpr int TPITCH = 80;
static constexpr int TILE_B = 128 * TPITCH;
static constexpr int BUF_B  = 4 * TILE_B;

__device__ __forceinline__ void ldtile_async(uint32_t sdst,
                                             const __nv_bfloat16* __restrict__ g,
                                             int row0, int k0, int ldk, int tid)
{
#pragma unroll
    for (int it = 0; it < 2; it++) {
        const int idx = tid + it * 256;
        const int r = idx >> 2, c = idx & 3;
        CP_ASYNC16(sdst + r * TPITCH + c * 16,
                   g + (size_t)(row0 + r) * ldk + k0 + c * 8);
    }
}

template<bool LORA, bool SPLITOUT>
__global__ __launch_bounds__(256, 1) void gemm_mma(
    const __nv_bfloat16* __restrict__ Ah, const __nv_bfloat16* __restrict__ Al,
    const __nv_bfloat16* __restrict__ Bh, const __nv_bfloat16* __restrict__ Bl,
    const float* __restrict__ bias,
    const float* __restrict__ xa, const float* __restrict__ BlLora,
    float* __restrict__ C,
    __nv_bfloat16* __restrict__ Ch, __nv_bfloat16* __restrict__ Cl,
    int M, int N, int K)
{
    extern __shared__ char smem[];
    const uint32_t sb = smem_u32(smem);
    const int tid = threadIdx.x;
    const int warp = tid >> 5, lane = tid & 31;
    const int wm = warp & 1, wn = warp >> 1;
    const int bn = blockIdx.x, bm = blockIdx.y;

    float acc[4][4][4];
#pragma unroll
    for (int mi = 0; mi < 4; mi++)
#pragma unroll
        for (int ni = 0; ni < 4; ni++)
#pragma unroll
            for (int e = 0; e < 4; e++) acc[mi][ni][e] = 0.f;

    const int nit = K >> 5;

    {
        const uint32_t s0 = sb;
        ldtile_async(s0,              Ah, bm * 128, 0, K, tid);
        ldtile_async(s0 + TILE_B,     Al, bm * 128, 0, K, tid);
        ldtile_async(s0 + 2 * TILE_B, Bh, bn * 128, 0, K, tid);
        ldtile_async(s0 + 3 * TILE_B, Bl, bn * 128, 0, K, tid);
        CP_COMMIT();
    }

    const uint32_t lrow = (uint32_t)(lane & 15) * TPITCH + (uint32_t)(lane >> 4) * 16;

    for (int it = 0; it < nit; it++) {
        if (it + 1 < nit) {
            const uint32_t s1 = sb + ((it + 1) & 1) * BUF_B;
            const int k1 = (it + 1) * 32;
            ldtile_async(s1,              Ah, bm * 128, k1, K, tid);
            ldtile_async(s1 + TILE_B,     Al, bm * 128, k1, K, tid);
            ldtile_async(s1 + 2 * TILE_B, Bh, bn * 128, k1, K, tid);
            ldtile_async(s1 + 3 * TILE_B, Bl, bn * 128, k1, K, tid);
            CP_COMMIT();
            CP_WAIT(1);
        } else {
            CP_WAIT(0);
        }
        __syncthreads();

        const uint32_t s0 = sb + (it & 1) * BUF_B;
        const uint32_t aBase = s0 + (wm * 64) * TPITCH + lrow;
        const uint32_t bBase = s0 + 2 * TILE_B + (wn * 32) * TPITCH + lrow;

#pragma unroll
        for (int kk = 0; kk < 2; kk++) {
            const uint32_t kOff = kk * 32;
            uint32_t ah[4][4], al[4][4], bh[4][2], bl[4][2];
#pragma unroll
            for (int mi = 0; mi < 4; mi++) {
                LDSM_X4(ah[mi][0], ah[mi][1], ah[mi][2], ah[mi][3],
                        aBase + mi * 16 * TPITCH + kOff);
                LDSM_X4(al[mi][0], al[mi][1], al[mi][2], al[mi][3],
                        aBase + TILE_B + mi * 16 * TPITCH + kOff);
            }
#pragma unroll
            for (int n2 = 0; n2 < 2; n2++) {
                uint32_t r0, r1, r2, r3;
                LDSM_X4(r0, r1, r2, r3, bBase + n2 * 16 * TPITCH + kOff);
                bh[n2 * 2][0] = r0; bh[n2 * 2][1] = r2;
                bh[n2 * 2 + 1][0] = r1; bh[n2 * 2 + 1][1] = r3;
                LDSM_X4(r0, r1, r2, r3, bBase + TILE_B + n2 * 16 * TPITCH + kOff);
                bl[n2 * 2][0] = r0; bl[n2 * 2][1] = r2;
                bl[n2 * 2 + 1][0] = r1; bl[n2 * 2 + 1][1] = r3;
            }
#pragma unroll
            for (int mi = 0; mi < 4; mi++)
#pragma unroll
                for (int ni = 0; ni < 4; ni++) {
                    mma16816(acc[mi][ni], ah[mi][0], ah[mi][1], ah[mi][2], ah[mi][3],
                             bh[ni][0], bh[ni][1]);
                    mma16816(acc[mi][ni], ah[mi][0], ah[mi][1], ah[mi][2], ah[mi][3],
                             bl[ni][0], bl[ni][1]);
                    mma16816(acc[mi][ni], al[mi][0], al[mi][1], al[mi][2], al[mi][3],
                             bh[ni][0], bh[ni][1]);
                }
        }
        __syncthreads();
    }

    float* blsm = (float*)smem;
    float* xasm = blsm + 1024;
    if (LORA) {
#pragma unroll
        for (int i = tid; i < 1024; i += 256) {
            blsm[i] = BlLora[(size_t)(i >> 7) * N + bn * 128 + (i & 127)] * 8.0f;
            xasm[i] = xa[(size_t)(bm * 128) * 8 + i];
        }
        __syncthreads();
    }

    const int g = lane >> 2, tig = lane & 3;
#pragma unroll
    for (int mi = 0; mi < 4; mi++) {
#pragma unroll
        for (int half = 0; half < 2; half++) {
            const int rloc = wm * 64 + mi * 16 + g + half * 8;
            const int grow = bm * 128 + rloc;
            float xv[8];
            if (LORA) {
#pragma unroll
                for (int r = 0; r < 8; r++) xv[r] = xasm[rloc * 8 + r];
            }
#pragma unroll
            for (int ni = 0; ni < 4; ni++) {
                const int cloc = wn * 32 + ni * 8 + tig * 2;
                float v0 = acc[mi][ni][half * 2 + 0] + bias[bn * 128 + cloc];
                float v1 = acc[mi][ni][half * 2 + 1] + bias[bn * 128 + cloc + 1];
                if (LORA) {
#pragma unroll
                    for (int r = 0; r < 8; r++) {
                        v0 = fmaf(xv[r], blsm[r * 128 + cloc],     v0);
                        v1 = fmaf(xv[r], blsm[r * 128 + cloc + 1], v1);
                    }
                }
                if (SPLITOUT) {
                    uint32_t hh, ll;
                    split2(v0, v1, hh, ll);
                    const size_t o2 = ((size_t)grow * N + bn * 128 + cloc) >> 1;
                    ((uint32_t*)Ch)[o2] = hh;
                    ((uint32_t*)Cl)[o2] = ll;
                } else {
                    float2 o; o.x = v0; o.y = v1;
                    *(float2*)(C + (size_t)grow * N + bn * 128 + cloc) = o;
                }
            }
        }
    }
}

// ---------------------------------------------------------------------------
// Flash attention (HMMA bf16 hi/lo split).  Block = 64 q-rows, 4 warps.
// smem tiles 64x64 bf16, pitch 72 elements (144B) -> conflict-free ldmatrix.
// K/V double-buffered via cp.async.
// ---------------------------------------------------------------------------
static constexpr int FPITB = 144;                 // bytes per smem row
static constexpr int FTILE = 64 * FPITB;          // 9216 B per tile
// layout: Qh, Ql, then 2 KV buffers of {Kh, Kl, Vh, Vl}
static constexpr int FSMEM = 2 * FTILE + 2 * 4 * FTILE;   // 92160 B

__device__ __forceinline__ void fl_tile_async(uint32_t sdst,
                                              const __nv_bfloat16* __restrict__ g,
                                              int row0, int tid)
{
#pragma unroll
    for (int i = 0; i < 4; i++) {
        const int idx = tid + i * 128;
        const int r = idx >> 3, c = idx & 7;
        CP_ASYNC16(sdst + r * FPITB + c * 16,
                   g + (size_t)(row0 + r) * 3072 + c * 8);
    }
}

__global__ __launch_bounds__(128) void flash_mma(
    const __nv_bfloat16* __restrict__ QKVh,
    const __nv_bfloat16* __restrict__ QKVl,
    __nv_bfloat16* __restrict__ Ch,
    __nv_bfloat16* __restrict__ Cl)
{
    extern __shared__ char smem[];
    const uint32_t sb = smem_u32(smem);
    const int tid = threadIdx.x, lane = tid & 31, warp = tid >> 5;
    const int qt = 31 - blockIdx.x, h = blockIdx.y, b = blockIdx.z;
    const int q0 = qt * 64;

    const __nv_bfloat16* qh_g = QKVh + (size_t)b * 2048 * 3072 + h * 64;
    const __nv_bfloat16* ql_g = QKVl + (size_t)b * 2048 * 3072 + h * 64;
    const __nv_bfloat16* kh_g = qh_g + 1024;
    const __nv_bfloat16* kl_g = ql_g + 1024;
    const __nv_bfloat16* vh_g = qh_g + 2048;
    const __nv_bfloat16* vl_g = ql_g + 2048;

    const uint32_t sQh = sb, sQl = sb + FTILE;
    const uint32_t sKV = sb + 2 * FTILE;

    // Q tiles then KV tile 0
    fl_tile_async(sQh, qh_g, q0, tid);
    fl_tile_async(sQl, ql_g, q0, tid);
    CP_COMMIT();
    fl_tile_async(sKV,             kh_g, 0, tid);
    fl_tile_async(sKV + FTILE,     kl_g, 0, tid);
    fl_tile_async(sKV + 2 * FTILE, vh_g, 0, tid);
    fl_tile_async(sKV + 3 * FTILE, vl_g, 0, tid);
    CP_COMMIT();

    CP_WAIT(1);          // Q complete
    __syncthreads();

    const uint32_t lA = (uint32_t)(lane & 15) * FPITB + (uint32_t)(lane >> 4) * 16;

    uint32_t qfh[4][4], qfl[4][4];
#pragma unroll
    for (int ks = 0; ks < 4; ks++) {
        LDSM_X4(qfh[ks][0], qfh[ks][1], qfh[ks][2], qfh[ks][3],
                sQh + (warp * 16) * FPITB + lA + ks * 32);
        LDSM_X4(qfl[ks][0], qfl[ks][1], qfl[ks][2], qfl[ks][3],
                sQl + (warp * 16) * FPITB + lA + ks * 32);
    }

    float oacc[8][4];
#pragma unroll
    for (int j = 0; j < 8; j++)
#pragma unroll
        for (int e = 0; e < 4; e++) oacc[j][e] = 0.f;
    float mrow[2] = {-3.0e38f, -3.0e38f};
    float lrow[2] = {0.f, 0.f};

    const int g = lane >> 2, tig = lane & 3;

    for (int kt = 0; kt <= qt; kt++) {
        CP_WAIT(0);
        __syncthreads();

        if (kt < qt) {          // prefetch next KV into the other buffer
            const uint32_t s1 = sKV + ((kt + 1) & 1) * (4 * FTILE);
            const int k1 = (kt + 1) * 64;
            fl_tile_async(s1,             kh_g, k1, tid);
            fl_tile_async(s1 + FTILE,     kl_g, k1, tid);
            fl_tile_async(s1 + 2 * FTILE, vh_g, k1, tid);
            fl_tile_async(s1 + 3 * FTILE, vl_g, k1, tid);
            CP_COMMIT();
        }

        const uint32_t sK = sKV + (kt & 1) * (4 * FTILE);
        const uint32_t sV = sK + 2 * FTILE;

        // ---- S = Q @ K^T (split) ----
        float sacc[8][4];
#pragma unroll
        for (int j = 0; j < 8; j++)
#pragma unroll
            for (int e = 0; e < 4; e++) sacc[j][e] = 0.f;

#pragma unroll
        for (int ks = 0; ks < 4; ks++) {
            uint32_t bh[8][2], bl[8][2];
#pragma unroll
            for (int ng = 0; ng < 4; ng++) {
                uint32_t r0, r1, r2, r3;
                LDSM_X4(r0, r1, r2, r3, sK + (ng * 16) * FPITB + lA + ks * 32);
                bh[ng * 2][0] = r0; bh[ng * 2][1] = r2;
                bh[ng * 2 + 1][0] = r1; bh[ng * 2 + 1][1] = r3;
                LDSM_X4(r0, r1, r2, r3, sK + FTILE + (ng * 16) * FPITB + lA + ks * 32);
                bl[ng * 2][0] = r0; bl[ng * 2][1] = r2;
                bl[ng * 2 + 1][0] = r1; bl[ng * 2 + 1][1] = r3;
            }
#pragma unroll
            for (int j = 0; j < 8; j++) {
                mma16816(sacc[j], qfh[ks][0], qfh[ks][1], qfh[ks][2], qfh[ks][3],
                         bh[j][0], bh[j][1]);
                mma16816(sacc[j], qfh[ks][0], qfh[ks][1], qfh[ks][2], qfh[ks][3],
                         bl[j][0], bl[j][1]);
                mma16816(sacc[j], qfl[ks][0], qfl[ks][1], qfl[ks][2], qfl[ks][3],
                         bh[j][0], bh[j][1]);
            }
        }

        // ---- scale + causal mask ----
        if (kt == qt) {
#pragma unroll
            for (int j = 0; j < 8; j++)
#pragma unroll
                for (int e = 0; e < 4; e++) {
                    const int col = j * 8 + tig * 2 + (e & 1);
                    const int row = warp * 16 + g + ((e >> 1) << 3);
                    sacc[j][e] = (col > row) ? -1.0e30f : sacc[j][e] * 0.125f;
                }
        } else {
#pragma unroll
            for (int j = 0; j < 8; j++)
#pragma unroll
                for (int e = 0; e < 4; e++) sacc[j][e] *= 0.125f;
        }

        // ---- online softmax (rows g and g+8) ----
        float tm0 = -3.0e38f, tm1 = -3.0e38f;
#pragma unroll
        for (int j = 0; j < 8; j++) {
            tm0 = fmaxf(tm0, fmaxf(sacc[j][0], sacc[j][1]));
            tm1 = fmaxf(tm1, fmaxf(sacc[j][2], sacc[j][3]));
        }
#pragma unroll
        for (int o = 1; o < 4; o <<= 1) {
            tm0 = fmaxf(tm0, __shfl_xor_sync(0xffffffffu, tm0, o));
            tm1 = fmaxf(tm1, __shfl_xor_sync(0xffffffffu, tm1, o));
        }
        const float nm0 = fmaxf(mrow[0], tm0);
        const float nm1 = fmaxf(mrow[1], tm1);
        const float c0 = __expf(mrow[0] - nm0);
        const float c1 = __expf(mrow[1] - nm1);
        mrow[0] = nm0; mrow[1] = nm1;

        float rs0 = 0.f, rs1 = 0.f;
#pragma unroll
        for (int j = 0; j < 8; j++) {
            sacc[j][0] = __expf(sacc[j][0] - nm0);
            sacc[j][1] = __expf(sacc[j][1] - nm0);
            sacc[j][2] = __expf(sacc[j][2] - nm1);
            sacc[j][3] = __expf(sacc[j][3] - nm1);
            rs0 += sacc[j][0] + sacc[j][1];
            rs1 += sacc[j][2] + sacc[j][3];
        }
#pragma unroll
        for (int o = 1; o < 4; o <<= 1) {
            rs0 += __shfl_xor_sync(0xffffffffu, rs0, o);
            rs1 += __shfl_xor_sync(0xffffffffu, rs1, o);
        }
        lrow[0] = lrow[0] * c0 + rs0;
        lrow[1] = lrow[1] * c1 + rs1;
#pragma unroll
        for (int j = 0; j < 8; j++) {
            oacc[j][0] *= c0; oacc[j][1] *= c0;
            oacc[j][2] *= c1; oacc[j][3] *= c1;
        }

        // ---- O += P @ V (split).  P A-frags from sacc via C->A identity ----
#pragma unroll
        for (int t = 0; t < 4; t++) {
            uint32_t ph[4], pl[4];
            split2(sacc[2 * t][0],     sacc[2 * t][1],     ph[0], pl[0]);
            split2(sacc[2 * t][2],     sacc[2 * t][3],     ph[1], pl[1]);
            split2(sacc[2 * t + 1][0], sacc[2 * t + 1][1], ph[2], pl[2]);
            split2(sacc[2 * t + 1][2], sacc[2 * t + 1][3], ph[3], pl[3]);
            const uint32_t vrow = (uint32_t)(t * 16 + (lane & 15)) * FPITB +
                                  ((lane & 16) ? 16u : 0u);
#pragma unroll
            for (int p = 0; p < 4; p++) {
                uint32_t vh0, vh1, vh2, vh3, vl0, vl1, vl2, vl3;
                LDSM_X4_T(vh0, vh1, vh2, vh3, sV + vrow + p * 32);
                LDSM_X4_T(vl0, vl1, vl2, vl3, sV + FTILE + vrow + p * 32);
                mma16816(oacc[2 * p],     ph[0], ph[1], ph[2], ph[3], vh0, vh1);
                mma16816(oacc[2 * p],     pl[0], pl[1], pl[2], pl[3], vh0, vh1);
                mma16816(oacc[2 * p],     ph[0], ph[1], ph[2], ph[3], vl0, vl1);
                mma16816(oacc[2 * p + 1], ph[0], ph[1], ph[2], ph[3], vh2, vh3);
                mma16816(oacc[2 * p + 1], pl[0], pl[1], pl[2], pl[3], vh2, vh3);
                mma16816(oacc[2 * p + 1], ph[0], ph[1], ph[2], ph[3], vl2, vl3);
            }
        }
    }

    // ---- normalize + write ctx hi/lo bf16 (merged heads [4096][1024]) ----
    const float inv0 = 1.0f / lrow[0];
    const float inv1 = 1.0f / lrow[1];
    const int row0 = b * 2048 + q0 + warp * 16 + g;
#pragma unroll
    for (int j = 0; j < 8; j++) {
        const int col = h * 64 + j * 8 + tig * 2;
        uint32_t hh, ll;
        split2(oacc[j][0] * inv0, oacc[j][1] * inv0, hh, ll);
        ((uint32_t*)Ch)[((size_t)row0 * 1024 + col) >> 1] = hh;
        ((uint32_t*)Cl)[((size_t)row0 * 1024 + col) >> 1] = ll;
        split2(oacc[j][2] * inv1, oacc[j][3] * inv1, hh, ll);
        ((uint32_t*)Ch)[((size_t)(row0 + 8) * 1024 + col) >> 1] = hh;
        ((uint32_t*)Cl)[((size_t)(row0 + 8) * 1024 + col) >> 1] = ll;
    }
}

// ---------------------------------------------------------------------------
// launch
// ---------------------------------------------------------------------------
extern "C" void kernel_launch(void* const* d_in, const int* in_sizes, int n_in,
                              void* d_out, int out_size)
{
    (void)in_sizes; (void)n_in; (void)out_size;
    const float* x     = (const float*)d_in[0];
    const float* Wqkv  = (const float*)d_in[1];
    const float* bqkv  = (const float*)d_in[2];
    const float* Alora = (const float*)d_in[3];
    const float* Blora = (const float*)d_in[4];
    const float* Wproj = (const float*)d_in[5];
    const float* bproj = (const float*)d_in[6];
    float* out = (float*)d_out;

    float* xa;
    __nv_bfloat16 *xh, *xl, *wqh, *wql, *wph, *wpl, *qh, *ql, *ch, *cl;
    cudaGetSymbolAddress((void**)&xa,  g_xa);
    cudaGetSymbolAddress((void**)&xh,  g_xh);
    cudaGetSymbolAddress((void**)&xl,  g_xl);
    cudaGetSymbolAddress((void**)&wqh, g_wqh);
    cudaGetSymbolAddress((void**)&wql, g_wql);
    cudaGetSymbolAddress((void**)&wph, g_wph);
    cudaGetSymbolAddress((void**)&wpl, g_wpl);
    cudaGetSymbolAddress((void**)&qh,  g_qh);
    cudaGetSymbolAddress((void**)&ql,  g_ql);
    cudaGetSymbolAddress((void**)&ch,  g_ch);
    cudaGetSymbolAddress((void**)&cl,  g_cl);

    const int gemm_smem = 2 * BUF_B;
    cudaFuncSetAttribute(gemm_mma<true, true>,
                         cudaFuncAttributeMaxDynamicSharedMemorySize, gemm_smem);
    cudaFuncSetAttribute(gemm_mma<false, false>,
                         cudaFuncAttributeMaxDynamicSharedMemorySize, gemm_smem);
    cudaFuncSetAttribute(flash_mma,
                         cudaFuncAttributeMaxDynamicSharedMemorySize, FSMEM);

    // prep
    split_bf16<<<4096, 256>>>((const float4*)x, (__nv_bfloat162*)xh,
                              (__nv_bfloat162*)xl, 4096 * 1024 / 4);
    transpose_split<<<dim3(96, 32), dim3(32, 8)>>>(Wqkv, wqh, wql, 1024, 3072);
    transpose_split<<<dim3(32, 32), dim3(32, 8)>>>(Wproj, wph, wpl, 1024, 1024);
    xa_kernel<<<4096, 128>>>(x, Alora, xa);

    // qkv = x @ Wqkv + b + ALPHA*(xa @ Blora)  -> bf16 hi/lo
    gemm_mma<true, true><<<dim3(24, 32), 256, gemm_smem>>>(
        xh, xl, wqh, wql, bqkv, xa, Blora,
        nullptr, qh, ql, 4096, 3072, 1024);

    // attention -> ctx hi/lo bf16
    flash_mma<<<dim3(32, 16, 2), 128, FSMEM>>>(qh, ql, ch, cl);

    // out = ctx @ Wproj + b  (fp32)
    gemm_mma<false, false><<<dim3(8, 32), 256, gemm_smem>>>(
        ch, cl, wph, wpl, bproj, nullptr, nullptr,
        out, nullptr, nullptr, 4096, 1024, 1024);
}